// round 4
// baseline (speedup 1.0000x reference)
#include <cuda_runtime.h>
#include <math.h>
#include <stdint.h>

#define NN 100000
#define EE 6400000
#define RR 90

// ---------------- static device scratch (allocation-free rule) ----------------
__device__ int    g_cnt[(size_t)NN * RR];   // counts, then 1/cnt as float bits (36 MB)
__device__ int    g_deg[NN];                // per-dst degree
__device__ int    g_off[NN + 1];            // CSR offsets
__device__ int    g_cursor[NN];             // scatter cursors (copy of offsets)
__device__ int    g_sorted[EE];             // dst-sorted packed (src<<7 | rel)
__device__ float4 g_x4[NN];                 // x padded to 4
__device__ float4 g_h1[(size_t)NN * 2];     // h1, stride 8 floats (6 used + 2 pad)
__device__ float4 g_h2[NN];                 // h2, stride 4 floats (3 used + 1 pad)
__device__ float  g_pool[8];

// ---------------- zero counts + pool ----------------
__global__ void zero_cnt() {
    int idx = blockIdx.x * blockDim.x + threadIdx.x;
    int stride = gridDim.x * blockDim.x;
    int4* c = (int4*)g_cnt;
    const int n4 = (NN * RR) / 4;
    for (int i = idx; i < n4; i += stride) c[i] = make_int4(0, 0, 0, 0);
    if (idx < 8) g_pool[idx] = 0.f;
}

// ---------------- pad x [N,3] -> float4 ----------------
__global__ void pad_x(const float* __restrict__ x) {
    int i = blockIdx.x * blockDim.x + threadIdx.x;
    if (i < NN) g_x4[i] = make_float4(x[i * 3], x[i * 3 + 1], x[i * 3 + 2], 0.f);
}

// ---------------- count pass: cnt[dst*R + et]++ ----------------
__global__ void count_k(const int* __restrict__ dst, const int* __restrict__ et) {
    const int4* d4 = (const int4*)dst;
    const int4* e4 = (const int4*)et;
    const int n4 = EE / 4;
    int stride = gridDim.x * blockDim.x;
    for (int i = blockIdx.x * blockDim.x + threadIdx.x; i < n4; i += stride) {
        int4 d = d4[i];
        int4 e = e4[i];
        atomicAdd(&g_cnt[d.x * RR + e.x], 1);
        atomicAdd(&g_cnt[d.y * RR + e.y], 1);
        atomicAdd(&g_cnt[d.z * RR + e.z], 1);
        atomicAdd(&g_cnt[d.w * RR + e.w], 1);
    }
}

// ---------------- per-node: degree = row sum; counts -> reciprocal (in place) ----------------
__global__ void deg_inv() {
    int gw = (blockIdx.x * blockDim.x + threadIdx.x) >> 5;
    int lane = threadIdx.x & 31;
    if (gw >= NN) return;
    size_t base = (size_t)gw * RR;
    int s = 0;
    for (int j = lane; j < RR; j += 32) {
        int c = g_cnt[base + j];
        s += c;
        g_cnt[base + j] = __float_as_int(c > 0 ? 1.f / (float)c : 0.f);
    }
#pragma unroll
    for (int o = 16; o; o >>= 1) s += __shfl_down_sync(0xffffffffu, s, o);
    if (lane == 0) g_deg[gw] = s;
}

// ---------------- single-block exclusive scan: deg -> off (+cursor copy) ----------------
__global__ void scan_k() {
    __shared__ int warp_sums[32];
    __shared__ int s_carry;
    int tid = threadIdx.x, lane = tid & 31, wid = tid >> 5;
    if (tid == 0) s_carry = 0;
    __syncthreads();
    for (int base = 0; base < NN; base += 1024) {
        int i = base + tid;
        int v = (i < NN) ? g_deg[i] : 0;
        int x = v;
#pragma unroll
        for (int d = 1; d < 32; d <<= 1) {
            int y = __shfl_up_sync(0xffffffffu, x, d);
            if (lane >= d) x += y;
        }
        if (lane == 31) warp_sums[wid] = x;
        __syncthreads();
        if (wid == 0) {
            int w = warp_sums[lane];
#pragma unroll
            for (int d = 1; d < 32; d <<= 1) {
                int y = __shfl_up_sync(0xffffffffu, w, d);
                if (lane >= d) w += y;
            }
            warp_sums[lane] = w;
        }
        __syncthreads();
        int incl = x + (wid > 0 ? warp_sums[wid - 1] : 0);
        int carry = s_carry;
        if (i < NN) {
            int off = carry + incl - v;
            g_off[i] = off;
            g_cursor[i] = off;
        }
        __syncthreads();
        if (tid == 0) s_carry = carry + warp_sums[31];
        __syncthreads();
    }
    if (threadIdx.x == 0) g_off[NN] = s_carry;
}

// ---------------- counting-sort scatter: g_sorted[pos] = src<<7 | rel ----------------
__global__ void scatter_k(const int* __restrict__ src, const int* __restrict__ dst,
                          const int* __restrict__ et) {
    const int4* s4 = (const int4*)src;
    const int4* d4 = (const int4*)dst;
    const int4* e4 = (const int4*)et;
    const int n4 = EE / 4;
    int stride = gridDim.x * blockDim.x;
    for (int i = blockIdx.x * blockDim.x + threadIdx.x; i < n4; i += stride) {
        int4 s = s4[i];
        int4 d = d4[i];
        int4 t = e4[i];
        int p0 = atomicAdd(&g_cursor[d.x], 1);
        int p1 = atomicAdd(&g_cursor[d.y], 1);
        int p2 = atomicAdd(&g_cursor[d.z], 1);
        int p3 = atomicAdd(&g_cursor[d.w], 1);
        g_sorted[p0] = (s.x << 7) | t.x;
        g_sorted[p1] = (s.y << 7) | t.y;
        g_sorted[p2] = (s.z << 7) | t.z;
        g_sorted[p3] = (s.w << 7) | t.w;
    }
}

// ---------------- layer 1: mean aggr (3 -> 6) + root + relu, warp per node ----------------
__global__ void layer1_k(const float* __restrict__ W, const float* __restrict__ root,
                         const float* __restrict__ bias) {
    __shared__ float sW[RR * 6];
    __shared__ float sR[18], sB[6];
    for (int i = threadIdx.x; i < RR * 6; i += blockDim.x) sW[i] = W[i];
    if (threadIdx.x < 18) sR[threadIdx.x] = root[threadIdx.x];
    if (threadIdx.x < 6) sB[threadIdx.x] = bias[threadIdx.x];
    __syncthreads();
    int gw = (blockIdx.x * blockDim.x + threadIdx.x) >> 5;
    if (gw >= NN) return;
    int lane = threadIdx.x & 31;
    int beg = g_off[gw], end = g_off[gw + 1];
    const int* invRow = g_cnt + (size_t)gw * RR;
    float a0 = 0, a1 = 0, a2 = 0, a3 = 0, a4 = 0, a5 = 0;
    for (int e = beg + lane; e < end; e += 32) {
        int p = g_sorted[e];
        int s = p >> 7, r = p & 127;
        float4 xv = g_x4[s];
        float iv = __int_as_float(invRow[r]);
        const float* w = sW + r * 6;
        float t0 = xv.x * iv, t1 = xv.y * iv, t2 = xv.z * iv;
        a0 += t0 * w[0]; a1 += t0 * w[1];
        a2 += t1 * w[2]; a3 += t1 * w[3];
        a4 += t2 * w[4]; a5 += t2 * w[5];
    }
#pragma unroll
    for (int o = 16; o; o >>= 1) {
        a0 += __shfl_down_sync(0xffffffffu, a0, o);
        a1 += __shfl_down_sync(0xffffffffu, a1, o);
        a2 += __shfl_down_sync(0xffffffffu, a2, o);
        a3 += __shfl_down_sync(0xffffffffu, a3, o);
        a4 += __shfl_down_sync(0xffffffffu, a4, o);
        a5 += __shfl_down_sync(0xffffffffu, a5, o);
    }
    if (lane == 0) {
        float4 xv = g_x4[gw];
        float h[6] = {a0, a1, a2, a3, a4, a5};
#pragma unroll
        for (int j = 0; j < 6; j++) {
            float v = h[j] + xv.x * sR[j] + xv.y * sR[6 + j] + xv.z * sR[12 + j] + sB[j];
            h[j] = v > 0.f ? v : 0.f;
        }
        g_h1[(size_t)gw * 2]     = make_float4(h[0], h[1], h[2], h[3]);
        g_h1[(size_t)gw * 2 + 1] = make_float4(h[4], h[5], 0.f, 0.f);
    }
}

// ---------------- layer 2: add aggr (6 -> 3) + root + relu, warp per node ----------------
__global__ void layer2_k(const float* __restrict__ W, const float* __restrict__ root,
                         const float* __restrict__ bias) {
    __shared__ float sW[RR * 6];
    __shared__ float sR[18], sB[3];
    for (int i = threadIdx.x; i < RR * 6; i += blockDim.x) sW[i] = W[i];
    if (threadIdx.x < 18) sR[threadIdx.x] = root[threadIdx.x];
    if (threadIdx.x < 3) sB[threadIdx.x] = bias[threadIdx.x];
    __syncthreads();
    int gw = (blockIdx.x * blockDim.x + threadIdx.x) >> 5;
    if (gw >= NN) return;
    int lane = threadIdx.x & 31;
    int beg = g_off[gw], end = g_off[gw + 1];
    float a0 = 0, a1 = 0, a2 = 0;
    for (int e = beg + lane; e < end; e += 32) {
        int p = g_sorted[e];
        int s = p >> 7, r = p & 127;
        float4 ha = g_h1[(size_t)s * 2];
        float4 hb = g_h1[(size_t)s * 2 + 1];
        const float* w = sW + r * 6;
        a0 += ha.x * w[0] + ha.y * w[1];
        a1 += ha.z * w[2] + ha.w * w[3];
        a2 += hb.x * w[4] + hb.y * w[5];
    }
#pragma unroll
    for (int o = 16; o; o >>= 1) {
        a0 += __shfl_down_sync(0xffffffffu, a0, o);
        a1 += __shfl_down_sync(0xffffffffu, a1, o);
        a2 += __shfl_down_sync(0xffffffffu, a2, o);
    }
    if (lane == 0) {
        float4 ha = g_h1[(size_t)gw * 2];
        float4 hb = g_h1[(size_t)gw * 2 + 1];
        float hin[6] = {ha.x, ha.y, ha.z, ha.w, hb.x, hb.y};
        float h[3] = {a0, a1, a2};
#pragma unroll
        for (int j = 0; j < 3; j++) {
            float v = h[j] + sB[j];
#pragma unroll
            for (int k = 0; k < 6; k++) v += hin[k] * sR[k * 3 + j];
            h[j] = v > 0.f ? v : 0.f;
        }
        g_h2[gw] = make_float4(h[0], h[1], h[2], 0.f);
    }
}

// ---------------- layer 3: mean aggr (3 -> 6) + root + relu + mean pool ----------------
__global__ void layer3_k(const float* __restrict__ W, const float* __restrict__ root,
                         const float* __restrict__ bias) {
    __shared__ float sW[RR * 6];
    __shared__ float sR[18], sB[6];
    __shared__ float sp[6];
    for (int i = threadIdx.x; i < RR * 6; i += blockDim.x) sW[i] = W[i];
    if (threadIdx.x < 18) sR[threadIdx.x] = root[threadIdx.x];
    if (threadIdx.x < 6) { sB[threadIdx.x] = bias[threadIdx.x]; sp[threadIdx.x] = 0.f; }
    __syncthreads();
    int gw = (blockIdx.x * blockDim.x + threadIdx.x) >> 5;
    int lane = threadIdx.x & 31;
    bool active = gw < NN;
    float a0 = 0, a1 = 0, a2 = 0, a3 = 0, a4 = 0, a5 = 0;
    if (active) {
        int beg = g_off[gw], end = g_off[gw + 1];
        const int* invRow = g_cnt + (size_t)gw * RR;
        for (int e = beg + lane; e < end; e += 32) {
            int p = g_sorted[e];
            int s = p >> 7, r = p & 127;
            float4 xv = g_h2[s];
            float iv = __int_as_float(invRow[r]);
            const float* w = sW + r * 6;
            float t0 = xv.x * iv, t1 = xv.y * iv, t2 = xv.z * iv;
            a0 += t0 * w[0]; a1 += t0 * w[1];
            a2 += t1 * w[2]; a3 += t1 * w[3];
            a4 += t2 * w[4]; a5 += t2 * w[5];
        }
#pragma unroll
        for (int o = 16; o; o >>= 1) {
            a0 += __shfl_down_sync(0xffffffffu, a0, o);
            a1 += __shfl_down_sync(0xffffffffu, a1, o);
            a2 += __shfl_down_sync(0xffffffffu, a2, o);
            a3 += __shfl_down_sync(0xffffffffu, a3, o);
            a4 += __shfl_down_sync(0xffffffffu, a4, o);
            a5 += __shfl_down_sync(0xffffffffu, a5, o);
        }
        if (lane == 0) {
            float4 xv = g_h2[gw];
            float h[6] = {a0, a1, a2, a3, a4, a5};
#pragma unroll
            for (int j = 0; j < 6; j++) {
                float v = h[j] + xv.x * sR[j] + xv.y * sR[6 + j] + xv.z * sR[12 + j] + sB[j];
                h[j] = v > 0.f ? v : 0.f;
                atomicAdd(&sp[j], h[j]);
            }
        }
    }
    __syncthreads();
    if (threadIdx.x < 6) atomicAdd(&g_pool[threadIdx.x], sp[threadIdx.x]);
}

// ---------------- finalize: pooled mean + log_softmax ----------------
__global__ void finalize(float* __restrict__ out) {
    float v[6];
#pragma unroll
    for (int j = 0; j < 6; j++) v[j] = g_pool[j] / (float)NN;
    float m = v[0];
#pragma unroll
    for (int j = 1; j < 6; j++) m = fmaxf(m, v[j]);
    float s = 0.f;
#pragma unroll
    for (int j = 0; j < 6; j++) s += expf(v[j] - m);
    float l = logf(s);
#pragma unroll
    for (int j = 0; j < 6; j++) out[j] = v[j] - m - l;
}

extern "C" void kernel_launch(void* const* d_in, const int* in_sizes, int n_in,
                              void* d_out, int out_size) {
    const float* x     = (const float*)d_in[0];
    const int*   ei    = (const int*)d_in[1];
    const int*   src   = ei;
    const int*   dst   = ei + EE;
    const int*   et    = (const int*)d_in[3];
    const float* W1    = (const float*)d_in[4];
    const float* root1 = (const float*)d_in[5];
    const float* b1    = (const float*)d_in[6];
    const float* W2    = (const float*)d_in[7];
    const float* root2 = (const float*)d_in[8];
    const float* b2    = (const float*)d_in[9];
    const float* W3    = (const float*)d_in[10];
    const float* root3 = (const float*)d_in[11];
    const float* b3    = (const float*)d_in[12];
    float* out = (float*)d_out;

    const int LAYER_BLOCKS = (NN * 32 + 511) / 512;      // warp per node, 512 threads
    const int DEG_BLOCKS   = (NN * 32 + 255) / 256;

    zero_cnt<<<2048, 256>>>();
    pad_x<<<(NN + 255) / 256, 256>>>(x);
    count_k<<<2048, 256>>>(dst, et);
    deg_inv<<<DEG_BLOCKS, 256>>>();
    scan_k<<<1, 1024>>>();
    scatter_k<<<2048, 256>>>(src, dst, et);

    layer1_k<<<LAYER_BLOCKS, 512>>>(W1, root1, b1);
    layer2_k<<<LAYER_BLOCKS, 512>>>(W2, root2, b2);
    layer3_k<<<LAYER_BLOCKS, 512>>>(W3, root3, b3);

    finalize<<<1, 1>>>(out);
}

// round 5
// speedup vs baseline: 1.2080x; 1.2080x over previous
#include <cuda_runtime.h>
#include <math.h>
#include <stdint.h>

#define NN 100000
#define EE 6400000
#define RR 90

// ---------------- static device scratch (allocation-free rule) ----------------
__device__ int    g_cnt[(size_t)NN * RR];   // per-(dst,rel) edge counts (36 MB)
__device__ int    g_deg[NN];                // per-dst degree
__device__ int2   g_range[NN];              // (beg, end) per node in g_sorted
__device__ int    g_cursor[NN];             // scatter cursors
__device__ int    g_total;                  // running offset counter
__device__ int    g_sorted[EE];             // dst-grouped packed (src<<7 | rel)
__device__ float4 g_x4[NN];                 // x padded to 4
__device__ float4 g_h1[(size_t)NN * 2];     // h1, stride 8 floats (6 used + 2 pad)
__device__ float4 g_h2[NN];                 // h2, stride 4 floats (3 used + 1 pad)
__device__ float  g_pool[8];

// ---------------- zero counts/deg/pool + pad x ----------------
__global__ void zero_pad(const float* __restrict__ x) {
    int idx = blockIdx.x * blockDim.x + threadIdx.x;
    int stride = gridDim.x * blockDim.x;
    int4* c = (int4*)g_cnt;
    const int n4 = (NN * RR) / 4;
    for (int i = idx; i < n4; i += stride) c[i] = make_int4(0, 0, 0, 0);
    for (int i = idx; i < NN; i += stride) {
        g_deg[i] = 0;
        g_x4[i] = make_float4(x[i * 3], x[i * 3 + 1], x[i * 3 + 2], 0.f);
    }
    if (idx < 8) g_pool[idx] = 0.f;
    if (idx == 0) g_total = 0;
}

// ---------------- count pass: cnt[dst*R+et]++ and deg[dst]++ ----------------
__global__ void count_deg(const int* __restrict__ dst, const int* __restrict__ et) {
    const int4* d4 = (const int4*)dst;
    const int4* e4 = (const int4*)et;
    const int n4 = EE / 4;
    int stride = gridDim.x * blockDim.x;
    for (int i = blockIdx.x * blockDim.x + threadIdx.x; i < n4; i += stride) {
        int4 d = d4[i];
        int4 e = e4[i];
        atomicAdd(&g_cnt[d.x * RR + e.x], 1);
        atomicAdd(&g_cnt[d.y * RR + e.y], 1);
        atomicAdd(&g_cnt[d.z * RR + e.z], 1);
        atomicAdd(&g_cnt[d.w * RR + e.w], 1);
        atomicAdd(&g_deg[d.x], 1);
        atomicAdd(&g_deg[d.y], 1);
        atomicAdd(&g_deg[d.z], 1);
        atomicAdd(&g_deg[d.w], 1);
    }
}

// ---------------- range assignment: warp-aggregated atomic (no scan needed) ----------------
// Node order inside g_sorted is irrelevant; any disjoint range assignment works.
__global__ void offsets_k() {
    int i = blockIdx.x * blockDim.x + threadIdx.x;
    if (i >= NN) return;               // NN % 32 == 0 -> whole warps exit together
    int lane = threadIdx.x & 31;
    int d = g_deg[i];
    int x = d;
#pragma unroll
    for (int o = 1; o < 32; o <<= 1) {
        int y = __shfl_up_sync(0xffffffffu, x, o);
        if (lane >= o) x += y;
    }
    int warptot = __shfl_sync(0xffffffffu, x, 31);
    int base = 0;
    if (lane == 31) base = atomicAdd(&g_total, warptot);
    base = __shfl_sync(0xffffffffu, base, 31);
    int beg = base + x - d;
    g_range[i] = make_int2(beg, beg + d);
    g_cursor[i] = beg;
}

// ---------------- counting-sort scatter: g_sorted[pos] = src<<7 | rel ----------------
__global__ void scatter_k(const int* __restrict__ src, const int* __restrict__ dst,
                          const int* __restrict__ et) {
    const int4* s4 = (const int4*)src;
    const int4* d4 = (const int4*)dst;
    const int4* e4 = (const int4*)et;
    const int n4 = EE / 4;
    int stride = gridDim.x * blockDim.x;
    for (int i = blockIdx.x * blockDim.x + threadIdx.x; i < n4; i += stride) {
        int4 s = s4[i];
        int4 d = d4[i];
        int4 t = e4[i];
        int p0 = atomicAdd(&g_cursor[d.x], 1);
        int p1 = atomicAdd(&g_cursor[d.y], 1);
        int p2 = atomicAdd(&g_cursor[d.z], 1);
        int p3 = atomicAdd(&g_cursor[d.w], 1);
        g_sorted[p0] = (s.x << 7) | t.x;
        g_sorted[p1] = (s.y << 7) | t.y;
        g_sorted[p2] = (s.z << 7) | t.z;
        g_sorted[p3] = (s.w << 7) | t.w;
    }
}

// ---------------- layer 1: mean aggr (3 -> 6) + root + relu, warp per node ----------------
__global__ void __launch_bounds__(256) layer1_k(const float* __restrict__ W,
                                                const float* __restrict__ root,
                                                const float* __restrict__ bias) {
    __shared__ float sW[RR * 6];
    __shared__ float sR[18], sB[6];
    for (int i = threadIdx.x; i < RR * 6; i += blockDim.x) sW[i] = W[i];
    if (threadIdx.x < 18) sR[threadIdx.x] = root[threadIdx.x];
    if (threadIdx.x < 6) sB[threadIdx.x] = bias[threadIdx.x];
    __syncthreads();
    int gw = (blockIdx.x * blockDim.x + threadIdx.x) >> 5;
    if (gw >= NN) return;
    int lane = threadIdx.x & 31;
    int2 rg = g_range[gw];
    const int* cntRow = g_cnt + (size_t)gw * RR;
    float a0 = 0, a1 = 0, a2 = 0, a3 = 0, a4 = 0, a5 = 0;
    int e = rg.x + lane;
    for (; e + 32 < rg.y; e += 64) {
        int p0 = g_sorted[e];
        int p1 = g_sorted[e + 32];
        float4 x0 = __ldg(&g_x4[p0 >> 7]);
        float4 x1 = __ldg(&g_x4[p1 >> 7]);
        float iv0 = __fdividef(1.f, (float)cntRow[p0 & 127]);
        float iv1 = __fdividef(1.f, (float)cntRow[p1 & 127]);
        const float* w0 = sW + (p0 & 127) * 6;
        const float* w1 = sW + (p1 & 127) * 6;
        float t0 = x0.x * iv0, t1 = x0.y * iv0, t2 = x0.z * iv0;
        a0 += t0 * w0[0]; a1 += t0 * w0[1];
        a2 += t1 * w0[2]; a3 += t1 * w0[3];
        a4 += t2 * w0[4]; a5 += t2 * w0[5];
        float u0 = x1.x * iv1, u1 = x1.y * iv1, u2 = x1.z * iv1;
        a0 += u0 * w1[0]; a1 += u0 * w1[1];
        a2 += u1 * w1[2]; a3 += u1 * w1[3];
        a4 += u2 * w1[4]; a5 += u2 * w1[5];
    }
    if (e < rg.y) {
        int p0 = g_sorted[e];
        float4 x0 = __ldg(&g_x4[p0 >> 7]);
        float iv0 = __fdividef(1.f, (float)cntRow[p0 & 127]);
        const float* w0 = sW + (p0 & 127) * 6;
        float t0 = x0.x * iv0, t1 = x0.y * iv0, t2 = x0.z * iv0;
        a0 += t0 * w0[0]; a1 += t0 * w0[1];
        a2 += t1 * w0[2]; a3 += t1 * w0[3];
        a4 += t2 * w0[4]; a5 += t2 * w0[5];
    }
#pragma unroll
    for (int o = 16; o; o >>= 1) {
        a0 += __shfl_down_sync(0xffffffffu, a0, o);
        a1 += __shfl_down_sync(0xffffffffu, a1, o);
        a2 += __shfl_down_sync(0xffffffffu, a2, o);
        a3 += __shfl_down_sync(0xffffffffu, a3, o);
        a4 += __shfl_down_sync(0xffffffffu, a4, o);
        a5 += __shfl_down_sync(0xffffffffu, a5, o);
    }
    if (lane == 0) {
        float4 xv = g_x4[gw];
        float h[6] = {a0, a1, a2, a3, a4, a5};
#pragma unroll
        for (int j = 0; j < 6; j++) {
            float v = h[j] + xv.x * sR[j] + xv.y * sR[6 + j] + xv.z * sR[12 + j] + sB[j];
            h[j] = v > 0.f ? v : 0.f;
        }
        g_h1[(size_t)gw * 2]     = make_float4(h[0], h[1], h[2], h[3]);
        g_h1[(size_t)gw * 2 + 1] = make_float4(h[4], h[5], 0.f, 0.f);
    }
}

// ---------------- layer 2: add aggr (6 -> 3) + root + relu, warp per node ----------------
__global__ void __launch_bounds__(256) layer2_k(const float* __restrict__ W,
                                                const float* __restrict__ root,
                                                const float* __restrict__ bias) {
    __shared__ float sW[RR * 6];
    __shared__ float sR[18], sB[3];
    for (int i = threadIdx.x; i < RR * 6; i += blockDim.x) sW[i] = W[i];
    if (threadIdx.x < 18) sR[threadIdx.x] = root[threadIdx.x];
    if (threadIdx.x < 3) sB[threadIdx.x] = bias[threadIdx.x];
    __syncthreads();
    int gw = (blockIdx.x * blockDim.x + threadIdx.x) >> 5;
    if (gw >= NN) return;
    int lane = threadIdx.x & 31;
    int2 rg = g_range[gw];
    float a0 = 0, a1 = 0, a2 = 0;
    int e = rg.x + lane;
    for (; e + 32 < rg.y; e += 64) {
        int p0 = g_sorted[e];
        int p1 = g_sorted[e + 32];
        int s0 = p0 >> 7, s1 = p1 >> 7;
        float4 ha0 = __ldg(&g_h1[(size_t)s0 * 2]);
        float4 hb0 = __ldg(&g_h1[(size_t)s0 * 2 + 1]);
        float4 ha1 = __ldg(&g_h1[(size_t)s1 * 2]);
        float4 hb1 = __ldg(&g_h1[(size_t)s1 * 2 + 1]);
        const float* w0 = sW + (p0 & 127) * 6;
        const float* w1 = sW + (p1 & 127) * 6;
        a0 += ha0.x * w0[0] + ha0.y * w0[1];
        a1 += ha0.z * w0[2] + ha0.w * w0[3];
        a2 += hb0.x * w0[4] + hb0.y * w0[5];
        a0 += ha1.x * w1[0] + ha1.y * w1[1];
        a1 += ha1.z * w1[2] + ha1.w * w1[3];
        a2 += hb1.x * w1[4] + hb1.y * w1[5];
    }
    if (e < rg.y) {
        int p0 = g_sorted[e];
        int s0 = p0 >> 7;
        float4 ha0 = __ldg(&g_h1[(size_t)s0 * 2]);
        float4 hb0 = __ldg(&g_h1[(size_t)s0 * 2 + 1]);
        const float* w0 = sW + (p0 & 127) * 6;
        a0 += ha0.x * w0[0] + ha0.y * w0[1];
        a1 += ha0.z * w0[2] + ha0.w * w0[3];
        a2 += hb0.x * w0[4] + hb0.y * w0[5];
    }
#pragma unroll
    for (int o = 16; o; o >>= 1) {
        a0 += __shfl_down_sync(0xffffffffu, a0, o);
        a1 += __shfl_down_sync(0xffffffffu, a1, o);
        a2 += __shfl_down_sync(0xffffffffu, a2, o);
    }
    if (lane == 0) {
        float4 ha = g_h1[(size_t)gw * 2];
        float4 hb = g_h1[(size_t)gw * 2 + 1];
        float hin[6] = {ha.x, ha.y, ha.z, ha.w, hb.x, hb.y};
        float h[3] = {a0, a1, a2};
#pragma unroll
        for (int j = 0; j < 3; j++) {
            float v = h[j] + sB[j];
#pragma unroll
            for (int k = 0; k < 6; k++) v += hin[k] * sR[k * 3 + j];
            h[j] = v > 0.f ? v : 0.f;
        }
        g_h2[gw] = make_float4(h[0], h[1], h[2], 0.f);
    }
}

// ---------------- layer 3: mean aggr (3 -> 6) + root + relu + mean pool ----------------
__global__ void __launch_bounds__(256) layer3_k(const float* __restrict__ W,
                                                const float* __restrict__ root,
                                                const float* __restrict__ bias) {
    __shared__ float sW[RR * 6];
    __shared__ float sR[18], sB[6];
    __shared__ float sp[6];
    for (int i = threadIdx.x; i < RR * 6; i += blockDim.x) sW[i] = W[i];
    if (threadIdx.x < 18) sR[threadIdx.x] = root[threadIdx.x];
    if (threadIdx.x < 6) { sB[threadIdx.x] = bias[threadIdx.x]; sp[threadIdx.x] = 0.f; }
    __syncthreads();
    int gw = (blockIdx.x * blockDim.x + threadIdx.x) >> 5;
    int lane = threadIdx.x & 31;
    if (gw < NN) {
        int2 rg = g_range[gw];
        const int* cntRow = g_cnt + (size_t)gw * RR;
        float a0 = 0, a1 = 0, a2 = 0, a3 = 0, a4 = 0, a5 = 0;
        int e = rg.x + lane;
        for (; e + 32 < rg.y; e += 64) {
            int p0 = g_sorted[e];
            int p1 = g_sorted[e + 32];
            float4 x0 = __ldg(&g_h2[p0 >> 7]);
            float4 x1 = __ldg(&g_h2[p1 >> 7]);
            float iv0 = __fdividef(1.f, (float)cntRow[p0 & 127]);
            float iv1 = __fdividef(1.f, (float)cntRow[p1 & 127]);
            const float* w0 = sW + (p0 & 127) * 6;
            const float* w1 = sW + (p1 & 127) * 6;
            float t0 = x0.x * iv0, t1 = x0.y * iv0, t2 = x0.z * iv0;
            a0 += t0 * w0[0]; a1 += t0 * w0[1];
            a2 += t1 * w0[2]; a3 += t1 * w0[3];
            a4 += t2 * w0[4]; a5 += t2 * w0[5];
            float u0 = x1.x * iv1, u1 = x1.y * iv1, u2 = x1.z * iv1;
            a0 += u0 * w1[0]; a1 += u0 * w1[1];
            a2 += u1 * w1[2]; a3 += u1 * w1[3];
            a4 += u2 * w1[4]; a5 += u2 * w1[5];
        }
        if (e < rg.y) {
            int p0 = g_sorted[e];
            float4 x0 = __ldg(&g_h2[p0 >> 7]);
            float iv0 = __fdividef(1.f, (float)cntRow[p0 & 127]);
            const float* w0 = sW + (p0 & 127) * 6;
            float t0 = x0.x * iv0, t1 = x0.y * iv0, t2 = x0.z * iv0;
            a0 += t0 * w0[0]; a1 += t0 * w0[1];
            a2 += t1 * w0[2]; a3 += t1 * w0[3];
            a4 += t2 * w0[4]; a5 += t2 * w0[5];
        }
#pragma unroll
        for (int o = 16; o; o >>= 1) {
            a0 += __shfl_down_sync(0xffffffffu, a0, o);
            a1 += __shfl_down_sync(0xffffffffu, a1, o);
            a2 += __shfl_down_sync(0xffffffffu, a2, o);
            a3 += __shfl_down_sync(0xffffffffu, a3, o);
            a4 += __shfl_down_sync(0xffffffffu, a4, o);
            a5 += __shfl_down_sync(0xffffffffu, a5, o);
        }
        if (lane == 0) {
            float4 xv = g_h2[gw];
            float h[6] = {a0, a1, a2, a3, a4, a5};
#pragma unroll
            for (int j = 0; j < 6; j++) {
                float v = h[j] + xv.x * sR[j] + xv.y * sR[6 + j] + xv.z * sR[12 + j] + sB[j];
                h[j] = v > 0.f ? v : 0.f;
                atomicAdd(&sp[j], h[j]);
            }
        }
    }
    __syncthreads();
    if (threadIdx.x < 6) atomicAdd(&g_pool[threadIdx.x], sp[threadIdx.x]);
}

// ---------------- finalize: pooled mean + log_softmax ----------------
__global__ void finalize(float* __restrict__ out) {
    float v[6];
#pragma unroll
    for (int j = 0; j < 6; j++) v[j] = g_pool[j] / (float)NN;
    float m = v[0];
#pragma unroll
    for (int j = 1; j < 6; j++) m = fmaxf(m, v[j]);
    float s = 0.f;
#pragma unroll
    for (int j = 0; j < 6; j++) s += expf(v[j] - m);
    float l = logf(s);
#pragma unroll
    for (int j = 0; j < 6; j++) out[j] = v[j] - m - l;
}

extern "C" void kernel_launch(void* const* d_in, const int* in_sizes, int n_in,
                              void* d_out, int out_size) {
    const float* x     = (const float*)d_in[0];
    const int*   ei    = (const int*)d_in[1];
    const int*   src   = ei;
    const int*   dst   = ei + EE;
    const int*   et    = (const int*)d_in[3];
    const float* W1    = (const float*)d_in[4];
    const float* root1 = (const float*)d_in[5];
    const float* b1    = (const float*)d_in[6];
    const float* W2    = (const float*)d_in[7];
    const float* root2 = (const float*)d_in[8];
    const float* b2    = (const float*)d_in[9];
    const float* W3    = (const float*)d_in[10];
    const float* root3 = (const float*)d_in[11];
    const float* b3    = (const float*)d_in[12];
    float* out = (float*)d_out;

    const int LAYER_BLOCKS = (NN * 32 + 255) / 256;   // warp per node

    zero_pad<<<2048, 256>>>(x);                        // 1
    count_deg<<<2048, 256>>>(dst, et);                 // 2
    offsets_k<<<(NN + 255) / 256, 256>>>();            // 3
    scatter_k<<<2048, 256>>>(src, dst, et);            // 4  <- profiled slot
    layer1_k<<<LAYER_BLOCKS, 256>>>(W1, root1, b1);    // 5
    layer2_k<<<LAYER_BLOCKS, 256>>>(W2, root2, b2);    // 6
    layer3_k<<<LAYER_BLOCKS, 256>>>(W3, root3, b3);    // 7
    finalize<<<1, 1>>>(out);                           // 8
}

// round 6
// speedup vs baseline: 1.2089x; 1.0008x over previous
#include <cuda_runtime.h>
#include <math.h>
#include <stdint.h>

#define NN 100000
#define EE 6400000
#define RR 90

// ---------------- static device scratch (allocation-free rule) ----------------
__device__ int    g_cnt[(size_t)NN * RR];   // per-(dst,rel) edge counts (36 MB)
__device__ int    g_deg[NN];                // per-dst degree
__device__ int2   g_range[NN];              // (beg, end) per node in g_sorted
__device__ int    g_cursor[NN];             // scatter cursors
__device__ int    g_total;                  // running offset counter
__device__ int    g_sorted[EE];             // dst-grouped packed (src<<7 | rel)
__device__ float4 g_x4[NN];                 // x padded to 4
__device__ float4 g_h1[(size_t)NN * 2];     // h1, stride 8 floats (6 used + 2 pad)
__device__ float4 g_h2[NN];                 // h2, stride 4 floats (3 used + 1 pad)
__device__ float  g_pool[8];

// ---------------- zero counts/deg/pool + pad x ----------------
__global__ void zero_pad(const float* __restrict__ x) {
    int idx = blockIdx.x * blockDim.x + threadIdx.x;
    int stride = gridDim.x * blockDim.x;
    int4* c = (int4*)g_cnt;
    const int n4 = (NN * RR) / 4;
    for (int i = idx; i < n4; i += stride) c[i] = make_int4(0, 0, 0, 0);
    for (int i = idx; i < NN; i += stride) {
        g_deg[i] = 0;
        g_x4[i] = make_float4(x[i * 3], x[i * 3 + 1], x[i * 3 + 2], 0.f);
    }
    if (idx < 8) g_pool[idx] = 0.f;
    if (idx == 0) g_total = 0;
}

// ---------------- count pass: cnt[dst*R+et]++ and deg[dst]++ ----------------
__global__ void count_deg(const int* __restrict__ dst, const int* __restrict__ et) {
    const int4* d4 = (const int4*)dst;
    const int4* e4 = (const int4*)et;
    const int n4 = EE / 4;
    int stride = gridDim.x * blockDim.x;
    for (int i = blockIdx.x * blockDim.x + threadIdx.x; i < n4; i += stride) {
        int4 d = d4[i];
        int4 e = e4[i];
        atomicAdd(&g_cnt[d.x * RR + e.x], 1);
        atomicAdd(&g_cnt[d.y * RR + e.y], 1);
        atomicAdd(&g_cnt[d.z * RR + e.z], 1);
        atomicAdd(&g_cnt[d.w * RR + e.w], 1);
        atomicAdd(&g_deg[d.x], 1);
        atomicAdd(&g_deg[d.y], 1);
        atomicAdd(&g_deg[d.z], 1);
        atomicAdd(&g_deg[d.w], 1);
    }
}

// ---------------- range assignment: warp-aggregated atomic (no scan needed) ----------------
// Node order inside g_sorted is irrelevant; any disjoint range assignment works.
__global__ void offsets_k() {
    int i = blockIdx.x * blockDim.x + threadIdx.x;
    if (i >= NN) return;               // NN % 32 == 0 -> whole warps exit together
    int lane = threadIdx.x & 31;
    int d = g_deg[i];
    int x = d;
#pragma unroll
    for (int o = 1; o < 32; o <<= 1) {
        int y = __shfl_up_sync(0xffffffffu, x, o);
        if (lane >= o) x += y;
    }
    int warptot = __shfl_sync(0xffffffffu, x, 31);
    int base = 0;
    if (lane == 31) base = atomicAdd(&g_total, warptot);
    base = __shfl_sync(0xffffffffu, base, 31);
    int beg = base + x - d;
    g_range[i] = make_int2(beg, beg + d);
    g_cursor[i] = beg;
}

// ---------------- counting-sort scatter: g_sorted[pos] = src<<7 | rel ----------------
__global__ void scatter_k(const int* __restrict__ src, const int* __restrict__ dst,
                          const int* __restrict__ et) {
    const int4* s4 = (const int4*)src;
    const int4* d4 = (const int4*)dst;
    const int4* e4 = (const int4*)et;
    const int n4 = EE / 4;
    int stride = gridDim.x * blockDim.x;
    for (int i = blockIdx.x * blockDim.x + threadIdx.x; i < n4; i += stride) {
        int4 s = s4[i];
        int4 d = d4[i];
        int4 t = e4[i];
        int p0 = atomicAdd(&g_cursor[d.x], 1);
        int p1 = atomicAdd(&g_cursor[d.y], 1);
        int p2 = atomicAdd(&g_cursor[d.z], 1);
        int p3 = atomicAdd(&g_cursor[d.w], 1);
        g_sorted[p0] = (s.x << 7) | t.x;
        g_sorted[p1] = (s.y << 7) | t.y;
        g_sorted[p2] = (s.z << 7) | t.z;
        g_sorted[p3] = (s.w << 7) | t.w;
    }
}

// ---------------- layer 1: mean aggr (3 -> 6) + root + relu, warp per node ----------------
__global__ void __launch_bounds__(256) layer1_k(const float* __restrict__ W,
                                                const float* __restrict__ root,
                                                const float* __restrict__ bias) {
    __shared__ float sW[RR * 6];
    __shared__ float sR[18], sB[6];
    for (int i = threadIdx.x; i < RR * 6; i += blockDim.x) sW[i] = W[i];
    if (threadIdx.x < 18) sR[threadIdx.x] = root[threadIdx.x];
    if (threadIdx.x < 6) sB[threadIdx.x] = bias[threadIdx.x];
    __syncthreads();
    int gw = (blockIdx.x * blockDim.x + threadIdx.x) >> 5;
    if (gw >= NN) return;
    int lane = threadIdx.x & 31;
    int2 rg = g_range[gw];
    const int* cntRow = g_cnt + (size_t)gw * RR;
    float a0 = 0, a1 = 0, a2 = 0, a3 = 0, a4 = 0, a5 = 0;
    int e = rg.x + lane;
    for (; e + 32 < rg.y; e += 64) {
        int p0 = g_sorted[e];
        int p1 = g_sorted[e + 32];
        float4 x0 = __ldg(&g_x4[p0 >> 7]);
        float4 x1 = __ldg(&g_x4[p1 >> 7]);
        float iv0 = __fdividef(1.f, (float)cntRow[p0 & 127]);
        float iv1 = __fdividef(1.f, (float)cntRow[p1 & 127]);
        const float* w0 = sW + (p0 & 127) * 6;
        const float* w1 = sW + (p1 & 127) * 6;
        float t0 = x0.x * iv0, t1 = x0.y * iv0, t2 = x0.z * iv0;
        a0 += t0 * w0[0]; a1 += t0 * w0[1];
        a2 += t1 * w0[2]; a3 += t1 * w0[3];
        a4 += t2 * w0[4]; a5 += t2 * w0[5];
        float u0 = x1.x * iv1, u1 = x1.y * iv1, u2 = x1.z * iv1;
        a0 += u0 * w1[0]; a1 += u0 * w1[1];
        a2 += u1 * w1[2]; a3 += u1 * w1[3];
        a4 += u2 * w1[4]; a5 += u2 * w1[5];
    }
    if (e < rg.y) {
        int p0 = g_sorted[e];
        float4 x0 = __ldg(&g_x4[p0 >> 7]);
        float iv0 = __fdividef(1.f, (float)cntRow[p0 & 127]);
        const float* w0 = sW + (p0 & 127) * 6;
        float t0 = x0.x * iv0, t1 = x0.y * iv0, t2 = x0.z * iv0;
        a0 += t0 * w0[0]; a1 += t0 * w0[1];
        a2 += t1 * w0[2]; a3 += t1 * w0[3];
        a4 += t2 * w0[4]; a5 += t2 * w0[5];
    }
#pragma unroll
    for (int o = 16; o; o >>= 1) {
        a0 += __shfl_down_sync(0xffffffffu, a0, o);
        a1 += __shfl_down_sync(0xffffffffu, a1, o);
        a2 += __shfl_down_sync(0xffffffffu, a2, o);
        a3 += __shfl_down_sync(0xffffffffu, a3, o);
        a4 += __shfl_down_sync(0xffffffffu, a4, o);
        a5 += __shfl_down_sync(0xffffffffu, a5, o);
    }
    if (lane == 0) {
        float4 xv = g_x4[gw];
        float h[6] = {a0, a1, a2, a3, a4, a5};
#pragma unroll
        for (int j = 0; j < 6; j++) {
            float v = h[j] + xv.x * sR[j] + xv.y * sR[6 + j] + xv.z * sR[12 + j] + sB[j];
            h[j] = v > 0.f ? v : 0.f;
        }
        g_h1[(size_t)gw * 2]     = make_float4(h[0], h[1], h[2], h[3]);
        g_h1[(size_t)gw * 2 + 1] = make_float4(h[4], h[5], 0.f, 0.f);
    }
}

// ---------------- layer 2: add aggr (6 -> 3) + root + relu, warp per node ----------------
__global__ void __launch_bounds__(256) layer2_k(const float* __restrict__ W,
                                                const float* __restrict__ root,
                                                const float* __restrict__ bias) {
    __shared__ float sW[RR * 6];
    __shared__ float sR[18], sB[3];
    for (int i = threadIdx.x; i < RR * 6; i += blockDim.x) sW[i] = W[i];
    if (threadIdx.x < 18) sR[threadIdx.x] = root[threadIdx.x];
    if (threadIdx.x < 3) sB[threadIdx.x] = bias[threadIdx.x];
    __syncthreads();
    int gw = (blockIdx.x * blockDim.x + threadIdx.x) >> 5;
    if (gw >= NN) return;
    int lane = threadIdx.x & 31;
    int2 rg = g_range[gw];
    float a0 = 0, a1 = 0, a2 = 0;
    int e = rg.x + lane;
    for (; e + 32 < rg.y; e += 64) {
        int p0 = g_sorted[e];
        int p1 = g_sorted[e + 32];
        int s0 = p0 >> 7, s1 = p1 >> 7;
        float4 ha0 = __ldg(&g_h1[(size_t)s0 * 2]);
        float4 hb0 = __ldg(&g_h1[(size_t)s0 * 2 + 1]);
        float4 ha1 = __ldg(&g_h1[(size_t)s1 * 2]);
        float4 hb1 = __ldg(&g_h1[(size_t)s1 * 2 + 1]);
        const float* w0 = sW + (p0 & 127) * 6;
        const float* w1 = sW + (p1 & 127) * 6;
        a0 += ha0.x * w0[0] + ha0.y * w0[1];
        a1 += ha0.z * w0[2] + ha0.w * w0[3];
        a2 += hb0.x * w0[4] + hb0.y * w0[5];
        a0 += ha1.x * w1[0] + ha1.y * w1[1];
        a1 += ha1.z * w1[2] + ha1.w * w1[3];
        a2 += hb1.x * w1[4] + hb1.y * w1[5];
    }
    if (e < rg.y) {
        int p0 = g_sorted[e];
        int s0 = p0 >> 7;
        float4 ha0 = __ldg(&g_h1[(size_t)s0 * 2]);
        float4 hb0 = __ldg(&g_h1[(size_t)s0 * 2 + 1]);
        const float* w0 = sW + (p0 & 127) * 6;
        a0 += ha0.x * w0[0] + ha0.y * w0[1];
        a1 += ha0.z * w0[2] + ha0.w * w0[3];
        a2 += hb0.x * w0[4] + hb0.y * w0[5];
    }
#pragma unroll
    for (int o = 16; o; o >>= 1) {
        a0 += __shfl_down_sync(0xffffffffu, a0, o);
        a1 += __shfl_down_sync(0xffffffffu, a1, o);
        a2 += __shfl_down_sync(0xffffffffu, a2, o);
    }
    if (lane == 0) {
        float4 ha = g_h1[(size_t)gw * 2];
        float4 hb = g_h1[(size_t)gw * 2 + 1];
        float hin[6] = {ha.x, ha.y, ha.z, ha.w, hb.x, hb.y};
        float h[3] = {a0, a1, a2};
#pragma unroll
        for (int j = 0; j < 3; j++) {
            float v = h[j] + sB[j];
#pragma unroll
            for (int k = 0; k < 6; k++) v += hin[k] * sR[k * 3 + j];
            h[j] = v > 0.f ? v : 0.f;
        }
        g_h2[gw] = make_float4(h[0], h[1], h[2], 0.f);
    }
}

// ---------------- layer 3: mean aggr (3 -> 6) + root + relu + mean pool ----------------
__global__ void __launch_bounds__(256) layer3_k(const float* __restrict__ W,
                                                const float* __restrict__ root,
                                                const float* __restrict__ bias) {
    __shared__ float sW[RR * 6];
    __shared__ float sR[18], sB[6];
    __shared__ float sp[6];
    for (int i = threadIdx.x; i < RR * 6; i += blockDim.x) sW[i] = W[i];
    if (threadIdx.x < 18) sR[threadIdx.x] = root[threadIdx.x];
    if (threadIdx.x < 6) { sB[threadIdx.x] = bias[threadIdx.x]; sp[threadIdx.x] = 0.f; }
    __syncthreads();
    int gw = (blockIdx.x * blockDim.x + threadIdx.x) >> 5;
    int lane = threadIdx.x & 31;
    if (gw < NN) {
        int2 rg = g_range[gw];
        const int* cntRow = g_cnt + (size_t)gw * RR;
        float a0 = 0, a1 = 0, a2 = 0, a3 = 0, a4 = 0, a5 = 0;
        int e = rg.x + lane;
        for (; e + 32 < rg.y; e += 64) {
            int p0 = g_sorted[e];
            int p1 = g_sorted[e + 32];
            float4 x0 = __ldg(&g_h2[p0 >> 7]);
            float4 x1 = __ldg(&g_h2[p1 >> 7]);
            float iv0 = __fdividef(1.f, (float)cntRow[p0 & 127]);
            float iv1 = __fdividef(1.f, (float)cntRow[p1 & 127]);
            const float* w0 = sW + (p0 & 127) * 6;
            const float* w1 = sW + (p1 & 127) * 6;
            float t0 = x0.x * iv0, t1 = x0.y * iv0, t2 = x0.z * iv0;
            a0 += t0 * w0[0]; a1 += t0 * w0[1];
            a2 += t1 * w0[2]; a3 += t1 * w0[3];
            a4 += t2 * w0[4]; a5 += t2 * w0[5];
            float u0 = x1.x * iv1, u1 = x1.y * iv1, u2 = x1.z * iv1;
            a0 += u0 * w1[0]; a1 += u0 * w1[1];
            a2 += u1 * w1[2]; a3 += u1 * w1[3];
            a4 += u2 * w1[4]; a5 += u2 * w1[5];
        }
        if (e < rg.y) {
            int p0 = g_sorted[e];
            float4 x0 = __ldg(&g_h2[p0 >> 7]);
            float iv0 = __fdividef(1.f, (float)cntRow[p0 & 127]);
            const float* w0 = sW + (p0 & 127) * 6;
            float t0 = x0.x * iv0, t1 = x0.y * iv0, t2 = x0.z * iv0;
            a0 += t0 * w0[0]; a1 += t0 * w0[1];
            a2 += t1 * w0[2]; a3 += t1 * w0[3];
            a4 += t2 * w0[4]; a5 += t2 * w0[5];
        }
#pragma unroll
        for (int o = 16; o; o >>= 1) {
            a0 += __shfl_down_sync(0xffffffffu, a0, o);
            a1 += __shfl_down_sync(0xffffffffu, a1, o);
            a2 += __shfl_down_sync(0xffffffffu, a2, o);
            a3 += __shfl_down_sync(0xffffffffu, a3, o);
            a4 += __shfl_down_sync(0xffffffffu, a4, o);
            a5 += __shfl_down_sync(0xffffffffu, a5, o);
        }
        if (lane == 0) {
            float4 xv = g_h2[gw];
            float h[6] = {a0, a1, a2, a3, a4, a5};
#pragma unroll
            for (int j = 0; j < 6; j++) {
                float v = h[j] + xv.x * sR[j] + xv.y * sR[6 + j] + xv.z * sR[12 + j] + sB[j];
                h[j] = v > 0.f ? v : 0.f;
                atomicAdd(&sp[j], h[j]);
            }
        }
    }
    __syncthreads();
    if (threadIdx.x < 6) atomicAdd(&g_pool[threadIdx.x], sp[threadIdx.x]);
}

// ---------------- finalize: pooled mean + log_softmax ----------------
__global__ void finalize(float* __restrict__ out) {
    float v[6];
#pragma unroll
    for (int j = 0; j < 6; j++) v[j] = g_pool[j] / (float)NN;
    float m = v[0];
#pragma unroll
    for (int j = 1; j < 6; j++) m = fmaxf(m, v[j]);
    float s = 0.f;
#pragma unroll
    for (int j = 0; j < 6; j++) s += expf(v[j] - m);
    float l = logf(s);
#pragma unroll
    for (int j = 0; j < 6; j++) out[j] = v[j] - m - l;
}

extern "C" void kernel_launch(void* const* d_in, const int* in_sizes, int n_in,
                              void* d_out, int out_size) {
    const float* x     = (const float*)d_in[0];
    const int*   ei    = (const int*)d_in[1];
    const int*   src   = ei;
    const int*   dst   = ei + EE;
    const int*   et    = (const int*)d_in[3];
    const float* W1    = (const float*)d_in[4];
    const float* root1 = (const float*)d_in[5];
    const float* b1    = (const float*)d_in[6];
    const float* W2    = (const float*)d_in[7];
    const float* root2 = (const float*)d_in[8];
    const float* b2    = (const float*)d_in[9];
    const float* W3    = (const float*)d_in[10];
    const float* root3 = (const float*)d_in[11];
    const float* b3    = (const float*)d_in[12];
    float* out = (float*)d_out;

    const int LAYER_BLOCKS = (NN * 32 + 255) / 256;   // warp per node

    zero_pad<<<2048, 256>>>(x);                        // 1
    count_deg<<<2048, 256>>>(dst, et);                 // 2
    offsets_k<<<(NN + 255) / 256, 256>>>();            // 3
    scatter_k<<<2048, 256>>>(src, dst, et);            // 4  <- profiled slot
    layer1_k<<<LAYER_BLOCKS, 256>>>(W1, root1, b1);    // 5
    layer2_k<<<LAYER_BLOCKS, 256>>>(W2, root2, b2);    // 6
    layer3_k<<<LAYER_BLOCKS, 256>>>(W3, root3, b3);    // 7
    finalize<<<1, 1>>>(out);                           // 8
}